// round 16
// baseline (speedup 1.0000x reference)
#include <cuda_runtime.h>
#include <cuda_fp16.h>
#include <cstdint>

#define DINLINE __device__ __forceinline__

// ============================ helpers ============================
DINLINE uint32_t smem_u32(const void* p) {
    uint32_t a;
    asm("{ .reg .u64 t; cvta.to.shared.u64 t, %1; cvt.u32.u64 %0, t; }" : "=r"(a) : "l"(p));
    return a;
}

DINLINE void cpa16(uint32_t dst, const void* src) {
    asm volatile("cp.async.cg.shared.global [%0], [%1], 16;"
                 :: "r"(dst), "l"(__cvta_generic_to_global(src)) : "memory");
}
#define CPA_COMMIT() asm volatile("cp.async.commit_group;" ::: "memory")
#define CPA_WAIT(n)  asm volatile("cp.async.wait_group %0;" :: "n"(n) : "memory")

// m16n8k16 fp16 HMMA, fp32 accumulate (target-portable, sm_80+)
DINLINE void mma16(float* d, uint32_t a0, uint32_t a1, uint32_t a2, uint32_t a3,
                   uint32_t b0, uint32_t b1) {
    asm volatile("mma.sync.aligned.m16n8k16.row.col.f32.f16.f16.f32 "
                 "{%0,%1,%2,%3}, {%4,%5,%6,%7}, {%8,%9}, {%0,%1,%2,%3};"
                 : "+f"(d[0]), "+f"(d[1]), "+f"(d[2]), "+f"(d[3])
                 : "r"(a0), "r"(a1), "r"(a2), "r"(a3), "r"(b0), "r"(b1));
}

DINLINE void lds64(uint32_t& lo, uint32_t& hi, uint32_t addr) {
    asm volatile("ld.shared.v2.b32 {%0,%1}, [%2];" : "=r"(lo), "=r"(hi) : "r"(addr));
}

DINLINE uint32_t h2u(__half2 h) { return *(uint32_t*)&h; }

// ============================ constants ============================
static constexpr int NN = 8192;
static constexpr int DD = 256;

// fp16 GEMM config (shared by gemm1 and ygemm): BM=64, BN=256, BK=32, 4 stages,
// 128 threads (4 warps, 1x4, warp tile 64x64). stage = A 4KB + B 16KB = 20KB.
static constexpr int STAGE1_BYTES = 20480;
static constexpr int SMEM1_BYTES  = 4 * STAGE1_BYTES;           // 81920 (2 CTAs/SM)

// scratch (allocation-free contract: __device__ globals)
__device__ float d_dis[NN];                    // (1 + rowsum(adj))^{-1/2}
__device__ float d_sup[(long)NN * DD];         // Y = x @ W^T (fp32)
__device__ uint4 d_adjh[(long)NN * NN / 8];    // (adj + I) fp16, fragment-word layout (128MB)
__device__ uint4 d_xTh[(long)NN * DD / 8];     // (diag(d)Y)^T fp16 fragment layout (4MB)
__device__ uint4 d_xh[(long)NN * DD / 8];      // x fp16 fragment layout (4MB)
__device__ uint4 d_Wh[DD * DD / 8];            // W fp16 fragment layout (128KB)
__device__ float d_part[2L * NN * DD];         // split-K partials of (adj+I) @ (diag(d)Y)

// ============================================================================
// Packing helper: 16 consecutive fp32 -> 2 uint4 in fragment-word order.
//   u0 = {h2(k0,k1), h2(k8,k9),  h2(k2,k3), h2(k10,k11)}
//   u1 = {h2(k4,k5), h2(k12,k13),h2(k6,k7), h2(k14,k15)}
// ============================================================================
DINLINE void pack16v(const float4 v0, const float4 v1, const float4 v2, const float4 v3,
                     uint4& u0, uint4& u1) {
    u0.x = h2u(__float22half2_rn(make_float2(v0.x, v0.y)));
    u0.y = h2u(__float22half2_rn(make_float2(v2.x, v2.y)));
    u0.z = h2u(__float22half2_rn(make_float2(v0.z, v0.w)));
    u0.w = h2u(__float22half2_rn(make_float2(v2.z, v2.w)));
    u1.x = h2u(__float22half2_rn(make_float2(v1.x, v1.y)));
    u1.y = h2u(__float22half2_rn(make_float2(v3.x, v3.y)));
    u1.z = h2u(__float22half2_rn(make_float2(v1.z, v1.w)));
    u1.w = h2u(__float22half2_rn(make_float2(v3.z, v3.w)));
}

// ============================================================================
// K0: fused rowsum + (adj+I)->fp16 conversion. pack16 scheme, all lanes active.
// Rowsum uses RAW adj (d = rsqrt(1+rowsum)); diagonal +1 applied AFTER the sum,
// before packing, so adjh = adj + I and the identity term rides the GEMM.
// ============================================================================
__global__ void prepass_kernel(const float* __restrict__ adj) {
    __shared__ float red[256];
    const long m = blockIdx.x;
    const int t = threadIdx.x;
    const float4* row = (const float4*)(adj + m * (long)NN);   // 2048 float4
    uint4* outrow = d_adjh + m * 1024;
    const int diagc = (int)(m >> 4);       // chunk holding the diagonal element
    const int diagp = (int)(m & 15);       // position within that chunk
    float s = 0.f;
#pragma unroll
    for (int u = 0; u < 2; u++) {
        int chunk = t + u * 256;              // 0..511, covers k=16*chunk..+15
        const float4* src = row + chunk * 4;
        float4 v0 = src[0], v1 = src[1], v2 = src[2], v3 = src[3];
        s += (v0.x + v0.y) + (v0.z + v0.w) + (v1.x + v1.y) + (v1.z + v1.w)
           + (v2.x + v2.y) + (v2.z + v2.w) + (v3.x + v3.y) + (v3.z + v3.w);
        if (chunk == diagc) {                 // add identity AFTER rowsum accumulation
            switch (diagp) {
                case 0:  v0.x += 1.f; break;  case 1:  v0.y += 1.f; break;
                case 2:  v0.z += 1.f; break;  case 3:  v0.w += 1.f; break;
                case 4:  v1.x += 1.f; break;  case 5:  v1.y += 1.f; break;
                case 6:  v1.z += 1.f; break;  case 7:  v1.w += 1.f; break;
                case 8:  v2.x += 1.f; break;  case 9:  v2.y += 1.f; break;
                case 10: v2.z += 1.f; break;  case 11: v2.w += 1.f; break;
                case 12: v3.x += 1.f; break;  case 13: v3.y += 1.f; break;
                case 14: v3.z += 1.f; break;  default: v3.w += 1.f; break;
            }
        }
        uint4 u0, u1;
        pack16v(v0, v1, v2, v3, u0, u1);
        outrow[chunk * 2]     = u0;
        outrow[chunk * 2 + 1] = u1;
    }
    red[t] = s;
    __syncthreads();
    for (int o = 128; o > 0; o >>= 1) {
        if (t < o) red[t] += red[t + o];
        __syncthreads();
    }
    if (t == 0) d_dis[m] = rsqrtf(1.0f + red[0]);
}

// K0b: x -> fp16 fragment layout (row-major chunks: row m stride 512B)
__global__ void xh_kernel(const float* __restrict__ x) {
    int idx = blockIdx.x * 256 + threadIdx.x;      // (m<<4) | chunk ; 131072 total
    int m = idx >> 4, c = idx & 15;
    const float4* src = (const float4*)(x + (long)m * DD + c * 16);
    uint4 u0, u1;
    pack16v(src[0], src[1], src[2], src[3], u0, u1);
    d_xh[(long)idx * 2] = u0;
    d_xh[(long)idx * 2 + 1] = u1;
}

// K0c: W -> fp16 B-fragment layout (chunk-major: chunk C stride 8KB, feature n 32B)
__global__ void wh_kernel(const float* __restrict__ W) {
    int idx = blockIdx.x * 256 + threadIdx.x;      // (n<<4) | chunk ; 4096 total
    int n = idx >> 4, c = idx & 15;
    const float4* src = (const float4*)(W + (long)n * DD + c * 16);
    uint4 u0, u1;
    pack16v(src[0], src[1], src[2], src[3], u0, u1);
    long w = (long)(c * 256 + n) * 2;
    d_Wh[w] = u0;
    d_Wh[w + 1] = u1;
}

// ============================ fragment buffers (proven) ============================
struct Frag {
    uint32_t a[4][4];
    uint32_t b[8][2];
};

DINLINE void prefetch_frag(Frag& F, uint32_t aAddr, uint32_t bAddr) {
#pragma unroll
    for (int g = 0; g < 8; g++)
        lds64(F.b[g][0], F.b[g][1], bAddr + g * 256);
#pragma unroll
    for (int f = 0; f < 4; f++) {
        lds64(F.a[f][0], F.a[f][2], aAddr + f * 512);
        lds64(F.a[f][1], F.a[f][3], aAddr + f * 512 + 256);
    }
}

DINLINE void mma_frag(float acc[4][8][4], const Frag& F) {
#pragma unroll
    for (int f = 0; f < 4; f++)
#pragma unroll
        for (int g = 0; g < 8; g++)
            mma16(acc[f][g], F.a[f][0], F.a[f][1], F.a[f][2], F.a[f][3],
                  F.b[g][0], F.b[g][1]);
}

// ============================ K1: YGEMM d_sup = x @ W^T (fp16, NK=8, proven) ============================
__global__ void __launch_bounds__(128, 2) ygemm_kernel() {
    extern __shared__ char smem[];
    const uint32_t sbase = smem_u32(smem);
    const int tid = threadIdx.x, lane = tid & 31, wid = tid >> 5;
    const int wn = wid;
    const int g4 = lane >> 2, c4 = lane & 3;
    const long m0 = (long)blockIdx.x * 64;
    const int NK = 8;                                // 256 / 32

    const char* asrc = ((const char*)d_xh) + m0 * 512;
    const char* bsrc = (const char*)d_Wh;

    const uint32_t aB = sbase + (uint32_t)(g4 * 32 + c4 * 8);
    const uint32_t bB = sbase + 4096u + (uint32_t)((wn * 64 + g4) * 32 + c4 * 8);

    float acc[4][8][4];
#pragma unroll
    for (int f = 0; f < 4; f++)
#pragma unroll
        for (int g = 0; g < 8; g++)
#pragma unroll
            for (int q = 0; q < 4; q++) acc[f][g][q] = 0.f;

    auto load_stage = [&](uint32_t soff_, int kt) {
        const uint32_t As = sbase + soff_;
        const uint32_t Bs = As + 4096;
#pragma unroll
        for (int u = 0; u < 2; u++) {
            int w = tid + u * 128;
            int c = w >> 7, m = (w >> 1) & 63, jh = w & 1;
            cpa16(As + (uint32_t)w * 16,
                  asrc + (long)m * 512 + kt * 64 + c * 32 + jh * 16);
        }
#pragma unroll
        for (int u = 0; u < 8; u++) {
            int w = tid + u * 128;
            cpa16(Bs + (uint32_t)w * 16, bsrc + (long)kt * 16384 + (long)w * 16);
        }
    };

    load_stage(0, 0);                  CPA_COMMIT();
    load_stage(STAGE1_BYTES, 1);       CPA_COMMIT();
    load_stage(2 * STAGE1_BYTES, 2);   CPA_COMMIT();
    CPA_WAIT(2);
    __syncthreads();

    Frag F0, F1;
    prefetch_frag(F0, aB, bB);

    uint32_t soff = 0;
    uint32_t loff = 3 * STAGE1_BYTES;

#pragma unroll 1
    for (int kt = 0; kt < NK; kt++) {
        if (kt + 3 < NK) load_stage(loff, kt + 3);
        CPA_COMMIT();
        loff = (loff == 3 * STAGE1_BYTES) ? 0 : loff + STAGE1_BYTES;

        const uint32_t aS = aB + soff;
        const uint32_t bS = bB + soff;
        soff = (soff == 3 * STAGE1_BYTES) ? 0 : soff + STAGE1_BYTES;

        prefetch_frag(F1, aS + 2048, bS + 8192);
        mma_frag(acc, F0);

        CPA_WAIT(2);
        __syncthreads();

        prefetch_frag(F0, aB + soff, bB + soff);
        mma_frag(acc, F1);
    }

    // epilogue: write Y fp32
#pragma unroll
    for (int f = 0; f < 4; f++) {
        int row = f * 16 + g4;
#pragma unroll
        for (int g = 0; g < 8; g++) {
            int col = wn * 64 + g * 8 + c4 * 2;
            *(float2*)(d_sup + (m0 + row) * DD + col) = make_float2(acc[f][g][0], acc[f][g][1]);
            *(float2*)(d_sup + (m0 + row + 8) * DD + col) = make_float2(acc[f][g][2], acc[f][g][3]);
        }
    }
}

// ============================ K2: (diag(d)Y)^T -> fp16 fragment layout ============================
// Tiled 64 nodes x 64 feats transpose: coalesced fp32 loads (d applied on load),
// SMEM staging, 32B-contiguous-per-thread / 1KB-per-warp packed fp16 writes.
// Output layout identical to before: uint2 idx = (C*256 + feature)*4 + j, where
// word j = fp16{ dY[16C+2j][f], dY[16C+2j+1][f] | dY[16C+2j+8][f], dY[16C+2j+9][f] }.
__global__ void __launch_bounds__(256, 4) txpose_kernel() {
    __shared__ float ts[64][65];
    const int t = threadIdx.x;
    const int n0 = blockIdx.x * 64;      // node tile
    const int f0 = blockIdx.y * 64;      // feature tile

    // load: thread t -> node row nl = t>>2, feats (t&3)*16 .. +15 (4 float4s)
    {
        const int nl = t >> 2;
        const int fl = (t & 3) * 16;
        const float dn = d_dis[n0 + nl];
        const float4* src = (const float4*)(d_sup + (long)(n0 + nl) * DD + f0 + fl);
#pragma unroll
        for (int q = 0; q < 4; q++) {
            float4 v = src[q];
            ts[nl][fl + q * 4 + 0] = v.x * dn;
            ts[nl][fl + q * 4 + 1] = v.y * dn;
            ts[nl][fl + q * 4 + 2] = v.z * dn;
            ts[nl][fl + q * 4 + 3] = v.w * dn;
        }
    }
    __syncthreads();

    // write: thread t -> chunk-local cl = t>>6 (4 chunks of 16 nodes), feature fl = t&63
    {
        const int cl = t >> 6;
        const int fl = t & 63;
        const int nb = cl * 16;
        const long base = ((long)(((n0 >> 4) + cl) * 256 + f0 + fl)) * 4;
        uint2* dst = ((uint2*)d_xTh) + base;
#pragma unroll
        for (int j = 0; j < 4; j++) {
            uint2 o;
            o.x = h2u(__float22half2_rn(make_float2(ts[nb + 2 * j][fl],     ts[nb + 2 * j + 1][fl])));
            o.y = h2u(__float22half2_rn(make_float2(ts[nb + 2 * j + 8][fl], ts[nb + 2 * j + 9][fl])));
            dst[j] = o;
        }
    }
}

// ============================ K3: GEMM1 (fp16) part[ks] = (adj+I)[m0:,ksK] @ (dY)[ksK,:] ============================
// R10-proven config (frozen): 128 threads, 4 warps (1x4), warp tile 64x64, BM=64,
// 2 CTAs/SM, 4-stage pipeline, split-K=2, grid 256.
__global__ void __launch_bounds__(128, 2) gemm1_kernel() {
    extern __shared__ char smem[];
    const uint32_t sbase = smem_u32(smem);
    const int tid = threadIdx.x, lane = tid & 31, wid = tid >> 5;
    const int wn = wid;
    const int g4 = lane >> 2, c4 = lane & 3;
    const int ks = blockIdx.x & 1;
    const long m0 = (long)(blockIdx.x >> 1) * 64;
    const int NK = 128;                              // 4096 / 32

    const char* asrc = ((const char*)d_adjh) + m0 * 16384 + (long)ks * 8192;
    const char* bsrc = ((const char*)d_xTh) + (long)ks * 2097152;

    const uint32_t aB = sbase + (uint32_t)(g4 * 32 + c4 * 8);
    const uint32_t bB = sbase + 4096u + (uint32_t)((wn * 64 + g4) * 32 + c4 * 8);

    float acc[4][8][4];
#pragma unroll
    for (int f = 0; f < 4; f++)
#pragma unroll
        for (int g = 0; g < 8; g++)
#pragma unroll
            for (int q = 0; q < 4; q++) acc[f][g][q] = 0.f;

    auto load_stage = [&](uint32_t soff_, int kt) {
        const uint32_t As = sbase + soff_;
        const uint32_t Bs = As + 4096;
#pragma unroll
        for (int u = 0; u < 2; u++) {
            int w = tid + u * 128;
            int c = w >> 7, m = (w >> 1) & 63, jh = w & 1;
            cpa16(As + (uint32_t)w * 16,
                  asrc + (long)m * 16384 + kt * 64 + c * 32 + jh * 16);
        }
#pragma unroll
        for (int u = 0; u < 8; u++) {
            int w = tid + u * 128;
            cpa16(Bs + (uint32_t)w * 16, bsrc + (long)kt * 16384 + (long)w * 16);
        }
    };

    load_stage(0, 0);                  CPA_COMMIT();
    load_stage(STAGE1_BYTES, 1);       CPA_COMMIT();
    load_stage(2 * STAGE1_BYTES, 2);   CPA_COMMIT();
    CPA_WAIT(2);
    __syncthreads();

    Frag F0, F1;
    prefetch_frag(F0, aB, bB);

    uint32_t soff = 0;
    uint32_t loff = 3 * STAGE1_BYTES;

#pragma unroll 1
    for (int kt = 0; kt < NK; kt++) {
        if (kt + 3 < NK) load_stage(loff, kt + 3);
        CPA_COMMIT();
        loff = (loff == 3 * STAGE1_BYTES) ? 0 : loff + STAGE1_BYTES;

        const uint32_t aS = aB + soff;
        const uint32_t bS = bB + soff;
        soff = (soff == 3 * STAGE1_BYTES) ? 0 : soff + STAGE1_BYTES;

        prefetch_frag(F1, aS + 2048, bS + 8192);
        mma_frag(acc, F0);

        CPA_WAIT(2);
        __syncthreads();

        prefetch_frag(F0, aB + soff, bB + soff);
        mma_frag(acc, F1);
    }

    float* pbase = d_part + (long)ks * NN * DD;
#pragma unroll
    for (int f = 0; f < 4; f++) {
        int row = f * 16 + g4;
#pragma unroll
        for (int g = 0; g < 8; g++) {
            int col = wn * 64 + g * 8 + c4 * 2;
            float2 lo = make_float2(acc[f][g][0], acc[f][g][1]);
            float2 hi = make_float2(acc[f][g][2], acc[f][g][3]);
            *(float2*)(pbase + (m0 + row) * DD + col) = lo;
            *(float2*)(pbase + (m0 + row + 8) * DD + col) = hi;
        }
    }
}

// ============================ K4: reduce out = relu(d*(p0+p1)) ============================
// Identity term now rides the GEMM (adjh = adj + I), so no d_sup read here.
__global__ void __launch_bounds__(256, 1) reduce_kernel(float* __restrict__ out) {
    long idx = ((long)blockIdx.x * 256 + threadIdx.x) * 4;   // float4 granularity
    long i = idx >> 8;                                       // row (DD=256)
    float di = d_dis[i];
    float4 p0 = *(const float4*)(d_part + idx);
    float4 p1 = *(const float4*)(d_part + (long)NN * DD + idx);
    float4 v;
    v.x = fmaxf(di * (p0.x + p1.x), 0.f);
    v.y = fmaxf(di * (p0.y + p1.y), 0.f);
    v.z = fmaxf(di * (p0.z + p1.z), 0.f);
    v.w = fmaxf(di * (p0.w + p1.w), 0.f);
    *(float4*)(out + idx) = v;
}

// ============================ host ============================
extern "C" void kernel_launch(void* const* d_in, const int* in_sizes, int n_in,
                              void* d_out, int out_size) {
    const float* x   = (const float*)d_in[0];   // [8192, 256]
    const float* adj = (const float*)d_in[1];   // [8192, 8192]
    const float* W   = (const float*)d_in[2];   // [256, 256]
    float* out = (float*)d_out;

    cudaFuncSetAttribute(gemm1_kernel, cudaFuncAttributeMaxDynamicSharedMemorySize, SMEM1_BYTES);
    cudaFuncSetAttribute(ygemm_kernel, cudaFuncAttributeMaxDynamicSharedMemorySize, SMEM1_BYTES);

    xh_kernel<<<NN * 16 / 256, 256>>>(x);
    wh_kernel<<<DD * 16 / 256, 256>>>(W);
    ygemm_kernel<<<128, 128, SMEM1_BYTES>>>();
    prepass_kernel<<<NN, 256>>>(adj);
    txpose_kernel<<<dim3(NN / 64, DD / 64), 256>>>();
    gemm1_kernel<<<256, 128, SMEM1_BYTES>>>();
    reduce_kernel<<<NN * DD / 1024, 256>>>(out);
}

// round 17
// speedup vs baseline: 1.0361x; 1.0361x over previous
#include <cuda_runtime.h>
#include <cuda_fp16.h>
#include <cstdint>

#define DINLINE __device__ __forceinline__

// ============================ helpers ============================
DINLINE uint32_t smem_u32(const void* p) {
    uint32_t a;
    asm("{ .reg .u64 t; cvta.to.shared.u64 t, %1; cvt.u32.u64 %0, t; }" : "=r"(a) : "l"(p));
    return a;
}

DINLINE void cpa16(uint32_t dst, const void* src) {
    asm volatile("cp.async.cg.shared.global [%0], [%1], 16;"
                 :: "r"(dst), "l"(__cvta_generic_to_global(src)) : "memory");
}
#define CPA_COMMIT() asm volatile("cp.async.commit_group;" ::: "memory")
#define CPA_WAIT(n)  asm volatile("cp.async.wait_group %0;" :: "n"(n) : "memory")

// m16n8k16 fp16 HMMA, fp32 accumulate (target-portable, sm_80+)
DINLINE void mma16(float* d, uint32_t a0, uint32_t a1, uint32_t a2, uint32_t a3,
                   uint32_t b0, uint32_t b1) {
    asm volatile("mma.sync.aligned.m16n8k16.row.col.f32.f16.f16.f32 "
                 "{%0,%1,%2,%3}, {%4,%5,%6,%7}, {%8,%9}, {%0,%1,%2,%3};"
                 : "+f"(d[0]), "+f"(d[1]), "+f"(d[2]), "+f"(d[3])
                 : "r"(a0), "r"(a1), "r"(a2), "r"(a3), "r"(b0), "r"(b1));
}

DINLINE void lds64(uint32_t& lo, uint32_t& hi, uint32_t addr) {
    asm volatile("ld.shared.v2.b32 {%0,%1}, [%2];" : "=r"(lo), "=r"(hi) : "r"(addr));
}

DINLINE uint32_t h2u(__half2 h) { return *(uint32_t*)&h; }

// ============================ constants ============================
static constexpr int NN = 8192;
static constexpr int DD = 256;

// fp16 GEMM config (shared by gemm1 and ygemm): BM=64, BN=256, BK=32, 4 stages,
// 128 threads (4 warps, 1x4, warp tile 64x64). stage = A 4KB + B 16KB = 20KB.
static constexpr int STAGE1_BYTES = 20480;
static constexpr int SMEM1_BYTES  = 4 * STAGE1_BYTES;           // 81920 (2 CTAs/SM)

// scratch (allocation-free contract: __device__ globals)
__device__ float d_dis[NN];                    // (1 + rowsum(adj))^{-1/2}
__device__ float d_sup[(long)NN * DD];         // Y = x @ W^T (fp32)
__device__ uint4 d_adjh[(long)NN * NN / 8];    // adj fp16, fragment-word layout (128MB)
__device__ uint4 d_xTh[(long)NN * DD / 8];     // (diag(d)Y)^T fp16 fragment layout (4MB)
__device__ uint4 d_xh[(long)NN * DD / 8];      // x fp16 fragment layout (4MB)
__device__ uint4 d_Wh[DD * DD / 8];            // W fp16 fragment layout (128KB)
__device__ float d_part[2L * NN * DD];         // split-K partials of adj @ (diag(d)Y)

// ============================================================================
// Packing helper: 16 consecutive fp32 -> 2 uint4 in fragment-word order.
//   u0 = {h2(k0,k1), h2(k8,k9),  h2(k2,k3), h2(k10,k11)}
//   u1 = {h2(k4,k5), h2(k12,k13),h2(k6,k7), h2(k14,k15)}
// ============================================================================
DINLINE void pack16v(const float4 v0, const float4 v1, const float4 v2, const float4 v3,
                     uint4& u0, uint4& u1) {
    u0.x = h2u(__float22half2_rn(make_float2(v0.x, v0.y)));
    u0.y = h2u(__float22half2_rn(make_float2(v2.x, v2.y)));
    u0.z = h2u(__float22half2_rn(make_float2(v0.z, v0.w)));
    u0.w = h2u(__float22half2_rn(make_float2(v2.z, v2.w)));
    u1.x = h2u(__float22half2_rn(make_float2(v1.x, v1.y)));
    u1.y = h2u(__float22half2_rn(make_float2(v3.x, v3.y)));
    u1.z = h2u(__float22half2_rn(make_float2(v1.z, v1.w)));
    u1.w = h2u(__float22half2_rn(make_float2(v3.z, v3.w)));
}

// ============================================================================
// K0: fused rowsum + adj->fp16 conversion — pack16 scheme, no shuffles,
// all lanes active. Thread t owns chunks t and t+256.
// ============================================================================
__global__ void prepass_kernel(const float* __restrict__ adj) {
    __shared__ float red[256];
    const long m = blockIdx.x;
    const int t = threadIdx.x;
    const float4* row = (const float4*)(adj + m * (long)NN);   // 2048 float4
    uint4* outrow = d_adjh + m * 1024;
    float s = 0.f;
#pragma unroll
    for (int u = 0; u < 2; u++) {
        int chunk = t + u * 256;              // 0..511, covers k=16*chunk..+15
        const float4* src = row + chunk * 4;
        float4 v0 = src[0], v1 = src[1], v2 = src[2], v3 = src[3];
        s += (v0.x + v0.y) + (v0.z + v0.w) + (v1.x + v1.y) + (v1.z + v1.w)
           + (v2.x + v2.y) + (v2.z + v2.w) + (v3.x + v3.y) + (v3.z + v3.w);
        uint4 u0, u1;
        pack16v(v0, v1, v2, v3, u0, u1);
        outrow[chunk * 2]     = u0;
        outrow[chunk * 2 + 1] = u1;
    }
    red[t] = s;
    __syncthreads();
    for (int o = 128; o > 0; o >>= 1) {
        if (t < o) red[t] += red[t + o];
        __syncthreads();
    }
    if (t == 0) d_dis[m] = rsqrtf(1.0f + red[0]);
}

// K0b: x -> fp16 fragment layout (row-major chunks: row m stride 512B)
__global__ void xh_kernel(const float* __restrict__ x) {
    int idx = blockIdx.x * 256 + threadIdx.x;      // (m<<4) | chunk ; 131072 total
    int m = idx >> 4, c = idx & 15;
    const float4* src = (const float4*)(x + (long)m * DD + c * 16);
    uint4 u0, u1;
    pack16v(src[0], src[1], src[2], src[3], u0, u1);
    d_xh[(long)idx * 2] = u0;
    d_xh[(long)idx * 2 + 1] = u1;
}

// K0c: W -> fp16 B-fragment layout (chunk-major: chunk C stride 8KB, feature n 32B)
__global__ void wh_kernel(const float* __restrict__ W) {
    int idx = blockIdx.x * 256 + threadIdx.x;      // (n<<4) | chunk ; 4096 total
    int n = idx >> 4, c = idx & 15;
    const float4* src = (const float4*)(W + (long)n * DD + c * 16);
    uint4 u0, u1;
    pack16v(src[0], src[1], src[2], src[3], u0, u1);
    long w = (long)(c * 256 + n) * 2;
    d_Wh[w] = u0;
    d_Wh[w + 1] = u1;
}

// ============================ fragment buffers (proven) ============================
struct Frag {
    uint32_t a[4][4];
    uint32_t b[8][2];
};

DINLINE void prefetch_frag(Frag& F, uint32_t aAddr, uint32_t bAddr) {
#pragma unroll
    for (int g = 0; g < 8; g++)
        lds64(F.b[g][0], F.b[g][1], bAddr + g * 256);
#pragma unroll
    for (int f = 0; f < 4; f++) {
        lds64(F.a[f][0], F.a[f][2], aAddr + f * 512);
        lds64(F.a[f][1], F.a[f][3], aAddr + f * 512 + 256);
    }
}

DINLINE void mma_frag(float acc[4][8][4], const Frag& F) {
#pragma unroll
    for (int f = 0; f < 4; f++)
#pragma unroll
        for (int g = 0; g < 8; g++)
            mma16(acc[f][g], F.a[f][0], F.a[f][1], F.a[f][2], F.a[f][3],
                  F.b[g][0], F.b[g][1]);
}

// ============================ K1: YGEMM d_sup = x @ W^T (fp16, NK=8, proven) ============================
__global__ void __launch_bounds__(128, 2) ygemm_kernel() {
    extern __shared__ char smem[];
    const uint32_t sbase = smem_u32(smem);
    const int tid = threadIdx.x, lane = tid & 31, wid = tid >> 5;
    const int wn = wid;
    const int g4 = lane >> 2, c4 = lane & 3;
    const long m0 = (long)blockIdx.x * 64;
    const int NK = 8;                                // 256 / 32

    const char* asrc = ((const char*)d_xh) + m0 * 512;
    const char* bsrc = (const char*)d_Wh;

    const uint32_t aB = sbase + (uint32_t)(g4 * 32 + c4 * 8);
    const uint32_t bB = sbase + 4096u + (uint32_t)((wn * 64 + g4) * 32 + c4 * 8);

    float acc[4][8][4];
#pragma unroll
    for (int f = 0; f < 4; f++)
#pragma unroll
        for (int g = 0; g < 8; g++)
#pragma unroll
            for (int q = 0; q < 4; q++) acc[f][g][q] = 0.f;

    auto load_stage = [&](uint32_t soff_, int kt) {
        const uint32_t As = sbase + soff_;
        const uint32_t Bs = As + 4096;
#pragma unroll
        for (int u = 0; u < 2; u++) {
            int w = tid + u * 128;
            int c = w >> 7, m = (w >> 1) & 63, jh = w & 1;
            cpa16(As + (uint32_t)w * 16,
                  asrc + (long)m * 512 + kt * 64 + c * 32 + jh * 16);
        }
#pragma unroll
        for (int u = 0; u < 8; u++) {
            int w = tid + u * 128;
            cpa16(Bs + (uint32_t)w * 16, bsrc + (long)kt * 16384 + (long)w * 16);
        }
    };

    load_stage(0, 0);                  CPA_COMMIT();
    load_stage(STAGE1_BYTES, 1);       CPA_COMMIT();
    load_stage(2 * STAGE1_BYTES, 2);   CPA_COMMIT();
    CPA_WAIT(2);
    __syncthreads();

    Frag F0, F1;
    prefetch_frag(F0, aB, bB);

    uint32_t soff = 0;
    uint32_t loff = 3 * STAGE1_BYTES;

#pragma unroll 1
    for (int kt = 0; kt < NK; kt++) {
        if (kt + 3 < NK) load_stage(loff, kt + 3);
        CPA_COMMIT();
        loff = (loff == 3 * STAGE1_BYTES) ? 0 : loff + STAGE1_BYTES;

        const uint32_t aS = aB + soff;
        const uint32_t bS = bB + soff;
        soff = (soff == 3 * STAGE1_BYTES) ? 0 : soff + STAGE1_BYTES;

        prefetch_frag(F1, aS + 2048, bS + 8192);
        mma_frag(acc, F0);

        CPA_WAIT(2);
        __syncthreads();

        prefetch_frag(F0, aB + soff, bB + soff);
        mma_frag(acc, F1);
    }

    // epilogue: write Y fp32
#pragma unroll
    for (int f = 0; f < 4; f++) {
        int row = f * 16 + g4;
#pragma unroll
        for (int g = 0; g < 8; g++) {
            int col = wn * 64 + g * 8 + c4 * 2;
            *(float2*)(d_sup + (m0 + row) * DD + col) = make_float2(acc[f][g][0], acc[f][g][1]);
            *(float2*)(d_sup + (m0 + row + 8) * DD + col) = make_float2(acc[f][g][2], acc[f][g][3]);
        }
    }
}

// ============================ K2: (diag(d)Y)^T -> fp16 fragment layout ============================
__global__ void txpose_kernel() {
    __shared__ float t[32][33];
    int n0 = blockIdx.x * 32, c0 = blockIdx.y * 32;
    int tx = threadIdx.x, ty = threadIdx.y;
#pragma unroll
    for (int u = 0; u < 4; u++) {
        int n = n0 + ty + u * 8;
        t[ty + u * 8][tx] = d_sup[(long)n * DD + c0 + tx] * d_dis[n];
    }
    __syncthreads();
    int w = ty * 32 + tx;
    int fl = w >> 3, sub = w & 7, cq = sub >> 2, j = sub & 3;
    int l0 = cq * 16 + 2 * j;
    uint2 o;
    o.x = h2u(__float22half2_rn(make_float2(t[l0][fl],     t[l0 + 1][fl])));
    o.y = h2u(__float22half2_rn(make_float2(t[l0 + 8][fl], t[l0 + 9][fl])));
    int C = (n0 >> 4) + cq;
    ((uint2*)d_xTh)[(C * 256 + c0 + fl) * 4 + j] = o;
}

// ============================ K3: GEMM1 (fp16) part[ks] = adj[m0:,ksK] @ (dY)[ksK,:] ============================
// R10-proven config (frozen): 128 threads, 4 warps (1x4), warp tile 64x64, BM=64,
// 2 CTAs/SM, 4-stage pipeline, split-K=2, grid 256.
__global__ void __launch_bounds__(128, 2) gemm1_kernel() {
    extern __shared__ char smem[];
    const uint32_t sbase = smem_u32(smem);
    const int tid = threadIdx.x, lane = tid & 31, wid = tid >> 5;
    const int wn = wid;
    const int g4 = lane >> 2, c4 = lane & 3;
    const int ks = blockIdx.x & 1;
    const long m0 = (long)(blockIdx.x >> 1) * 64;
    const int NK = 128;                              // 4096 / 32

    const char* asrc = ((const char*)d_adjh) + m0 * 16384 + (long)ks * 8192;
    const char* bsrc = ((const char*)d_xTh) + (long)ks * 2097152;

    const uint32_t aB = sbase + (uint32_t)(g4 * 32 + c4 * 8);
    const uint32_t bB = sbase + 4096u + (uint32_t)((wn * 64 + g4) * 32 + c4 * 8);

    float acc[4][8][4];
#pragma unroll
    for (int f = 0; f < 4; f++)
#pragma unroll
        for (int g = 0; g < 8; g++)
#pragma unroll
            for (int q = 0; q < 4; q++) acc[f][g][q] = 0.f;

    auto load_stage = [&](uint32_t soff_, int kt) {
        const uint32_t As = sbase + soff_;
        const uint32_t Bs = As + 4096;
#pragma unroll
        for (int u = 0; u < 2; u++) {
            int w = tid + u * 128;
            int c = w >> 7, m = (w >> 1) & 63, jh = w & 1;
            cpa16(As + (uint32_t)w * 16,
                  asrc + (long)m * 16384 + kt * 64 + c * 32 + jh * 16);
        }
#pragma unroll
        for (int u = 0; u < 8; u++) {
            int w = tid + u * 128;
            cpa16(Bs + (uint32_t)w * 16, bsrc + (long)kt * 16384 + (long)w * 16);
        }
    };

    load_stage(0, 0);                  CPA_COMMIT();
    load_stage(STAGE1_BYTES, 1);       CPA_COMMIT();
    load_stage(2 * STAGE1_BYTES, 2);   CPA_COMMIT();
    CPA_WAIT(2);
    __syncthreads();

    Frag F0, F1;
    prefetch_frag(F0, aB, bB);

    uint32_t soff = 0;
    uint32_t loff = 3 * STAGE1_BYTES;

#pragma unroll 1
    for (int kt = 0; kt < NK; kt++) {
        if (kt + 3 < NK) load_stage(loff, kt + 3);
        CPA_COMMIT();
        loff = (loff == 3 * STAGE1_BYTES) ? 0 : loff + STAGE1_BYTES;

        const uint32_t aS = aB + soff;
        const uint32_t bS = bB + soff;
        soff = (soff == 3 * STAGE1_BYTES) ? 0 : soff + STAGE1_BYTES;

        prefetch_frag(F1, aS + 2048, bS + 8192);
        mma_frag(acc, F0);

        CPA_WAIT(2);
        __syncthreads();

        prefetch_frag(F0, aB + soff, bB + soff);
        mma_frag(acc, F1);
    }

    float* pbase = d_part + (long)ks * NN * DD;
#pragma unroll
    for (int f = 0; f < 4; f++) {
        int row = f * 16 + g4;
#pragma unroll
        for (int g = 0; g < 8; g++) {
            int col = wn * 64 + g * 8 + c4 * 2;
            float2 lo = make_float2(acc[f][g][0], acc[f][g][1]);
            float2 hi = make_float2(acc[f][g][2], acc[f][g][3]);
            *(float2*)(pbase + (m0 + row) * DD + col) = lo;
            *(float2*)(pbase + (m0 + row + 8) * DD + col) = hi;
        }
    }
}

// ============================ K4: reduce out = relu(d*(p0+p1+d*Y)) ============================
__global__ void __launch_bounds__(256, 1) reduce_kernel(float* __restrict__ out) {
    long idx = ((long)blockIdx.x * 256 + threadIdx.x) * 4;   // float4 granularity
    long i = idx >> 8;                                       // row (DD=256)
    float di = d_dis[i];
    float4 p0 = *(const float4*)(d_part + idx);
    float4 p1 = *(const float4*)(d_part + (long)NN * DD + idx);
    float4 yv = *(const float4*)(d_sup + idx);
    float4 v;
    v.x = fmaxf(di * (p0.x + p1.x + di * yv.x), 0.f);
    v.y = fmaxf(di * (p0.y + p1.y + di * yv.y), 0.f);
    v.z = fmaxf(di * (p0.z + p1.z + di * yv.z), 0.f);
    v.w = fmaxf(di * (p0.w + p1.w + di * yv.w), 0.f);
    *(float4*)(out + idx) = v;
}

// ============================ host ============================
// Fork-join overlap: {xh, wh, ygemm} (x/W path) runs on a side stream concurrent
// with prepass (adj path) on the launch stream. Join before txpose, which needs
// both d_dis (prepass) and d_sup (ygemm). Stream/events are host-side objects
// created once; per-call device work is identical and fully captured via the
// event-edge fork/join pattern.
extern "C" void kernel_launch(void* const* d_in, const int* in_sizes, int n_in,
                              void* d_out, int out_size) {
    const float* x   = (const float*)d_in[0];   // [8192, 256]
    const float* adj = (const float*)d_in[1];   // [8192, 8192]
    const float* W   = (const float*)d_in[2];   // [256, 256]
    float* out = (float*)d_out;

    static cudaStream_t s_side = nullptr;
    static cudaEvent_t ev_fork = nullptr, ev_join = nullptr;
    if (s_side == nullptr) {
        cudaStreamCreateWithFlags(&s_side, cudaStreamNonBlocking);
        cudaEventCreateWithFlags(&ev_fork, cudaEventDisableTiming);
        cudaEventCreateWithFlags(&ev_join, cudaEventDisableTiming);
        cudaFuncSetAttribute(gemm1_kernel, cudaFuncAttributeMaxDynamicSharedMemorySize, SMEM1_BYTES);
        cudaFuncSetAttribute(ygemm_kernel, cudaFuncAttributeMaxDynamicSharedMemorySize, SMEM1_BYTES);
    }

    // fork: side stream inherits dependency on everything prior on stream 0
    cudaEventRecord(ev_fork, 0);
    cudaStreamWaitEvent(s_side, ev_fork, 0);

    // side chain (x/W path)
    xh_kernel<<<NN * 16 / 256, 256, 0, s_side>>>(x);
    wh_kernel<<<DD * 16 / 256, 256, 0, s_side>>>(W);
    ygemm_kernel<<<128, 128, SMEM1_BYTES, s_side>>>();
    cudaEventRecord(ev_join, s_side);

    // main chain (adj path), concurrent with side chain
    prepass_kernel<<<NN, 256>>>(adj);

    // join: txpose needs d_dis (main) + d_sup (side)
    cudaStreamWaitEvent(0, ev_join, 0);
    txpose_kernel<<<dim3(NN / 32, DD / 32), dim3(32, 8)>>>();
    gemm1_kernel<<<256, 128, SMEM1_BYTES>>>();
    reduce_kernel<<<NN * DD / 1024, 256>>>(out);
}